// round 1
// baseline (speedup 1.0000x reference)
#include <cuda_runtime.h>
#include <math.h>

#define NPTS 2097152

struct F3 { float x, y, z; };

__device__ __forceinline__ F3 f3(float a, float b, float c) { F3 r; r.x=a; r.y=b; r.z=c; return r; }

// Gather one texel (3 floats) from face-major cubemap tex laid out [6][R][R][3]
__device__ __forceinline__ F3 texel3(const float* __restrict__ base, int R, int y, int x) {
    const float* p = base + ((size_t)y * R + x) * 3;
    return f3(__ldg(p), __ldg(p + 1), __ldg(p + 2));
}

// Bilinear cubemap sample matching the reference exactly (per-face clamp, no seams)
__device__ __forceinline__ F3 sample_cube(const float* __restrict__ tex, int R, F3 d) {
    float ax = fabsf(d.x), ay = fabsf(d.y), az = fabsf(d.z);
    bool is_x = (ax >= ay) && (ax >= az);
    bool is_y = (!is_x) && (ay >= az);
    int face; float ma, u, v;
    if (is_x) {
        face = (d.x > 0.f) ? 0 : 1;
        ma = ax;
        u = (d.x > 0.f) ? -d.z : d.z;
        v = -d.y;
    } else if (is_y) {
        face = (d.y > 0.f) ? 2 : 3;
        ma = ay;
        u = d.x;
        v = (d.y > 0.f) ? d.z : -d.z;
    } else {
        face = (d.z > 0.f) ? 4 : 5;
        ma = az;
        u = (d.z > 0.f) ? d.x : -d.x;
        v = -d.y;
    }
    ma = fmaxf(ma, 1e-20f);
    float fu = (u / ma * 0.5f + 0.5f) * (float)R - 0.5f;
    float fv = (v / ma * 0.5f + 0.5f) * (float)R - 0.5f;

    float x0f = floorf(fu), y0f = floorf(fv);
    float tx = fu - x0f, ty = fv - y0f;
    int x0 = min(max((int)x0f, 0), R - 1);
    int x1 = min(x0 + 1, R - 1);
    int y0 = min(max((int)y0f, 0), R - 1);
    int y1 = min(y0 + 1, R - 1);

    const float* base = tex + (size_t)face * R * R * 3;
    F3 c00 = texel3(base, R, y0, x0);
    F3 c01 = texel3(base, R, y0, x1);
    F3 c10 = texel3(base, R, y1, x0);
    F3 c11 = texel3(base, R, y1, x1);

    float w00 = (1.f - tx) * (1.f - ty);
    float w01 = tx * (1.f - ty);
    float w10 = (1.f - tx) * ty;
    float w11 = tx * ty;
    return f3(c00.x*w00 + c01.x*w01 + c10.x*w10 + c11.x*w11,
              c00.y*w00 + c01.y*w01 + c10.y*w10 + c11.y*w11,
              c00.z*w00 + c01.z*w01 + c10.z*w10 + c11.z*w11);
}

__device__ __forceinline__ float srgb1(float x) {
    // x already clipped to [0,1]
    if (x <= 0.0031308f) return 12.92f * x;
    return 1.055f * powf(fmaxf(x, 0.0031308f), 1.0f / 2.4f) - 0.055f;
}

__global__ void envlight_kernel(
    const float* __restrict__ view_dir,
    const float* __restrict__ normal,
    const float* __restrict__ kd,
    const float* __restrict__ ks,
    const float* __restrict__ reflect_occ,
    const float* __restrict__ diffuse_map,
    const float* __restrict__ spec0,
    const float* __restrict__ spec1,
    const float* __restrict__ spec2,
    const float* __restrict__ spec3,
    const float* __restrict__ spec4,
    const float* __restrict__ spec5,
    const float* __restrict__ fg_lut,
    float* __restrict__ out,
    int n)
{
    int i = blockIdx.x * blockDim.x + threadIdx.x;
    if (i >= n) return;

    const float* vp = view_dir + 3 * (size_t)i;
    const float* np = normal + 3 * (size_t)i;
    const float* kdp = kd + 3 * (size_t)i;
    const float* ksp = ks + 3 * (size_t)i;
    F3 v = f3(vp[0], vp[1], vp[2]);
    F3 nrm = f3(np[0], np[1], np[2]);
    F3 kdv = f3(kdp[0], kdp[1], kdp[2]);
    float ks0 = ksp[0];
    float roughness = ksp[1];
    float metallic = ksp[2];
    float occ = reflect_occ[i];

    // spec/diff colors
    F3 spec_col = f3((1.f - metallic) * 0.04f + kdv.x * metallic,
                     (1.f - metallic) * 0.04f + kdv.y * metallic,
                     (1.f - metallic) * 0.04f + kdv.z * metallic);
    F3 diff_col = f3(kdv.x * (1.f - metallic), kdv.y * (1.f - metallic), kdv.z * (1.f - metallic));

    // reflect + safe normalize
    float vdotn = v.x * nrm.x + v.y * nrm.y + v.z * nrm.z;
    F3 refl = f3(2.f * vdotn * nrm.x - v.x,
                 2.f * vdotn * nrm.y - v.y,
                 2.f * vdotn * nrm.z - v.z);
    float rr = refl.x * refl.x + refl.y * refl.y + refl.z * refl.z;
    rr = fmaxf(rr, 1e-20f);
    float inv = rsqrtf(rr);
    // match jnp: x / sqrt(...) -> use division for closer numerics
    float s = sqrtf(rr);
    refl = f3(refl.x / s, refl.y / s, refl.z / s);
    (void)inv;

    // diffuse term
    F3 diffuse = sample_cube(diffuse_map, 16, nrm);
    diffuse = f3(fmaxf(diffuse.x, 0.f), fmaxf(diffuse.y, 0.f), fmaxf(diffuse.z, 0.f));
    float kdocc = 1.f - ks0;
    F3 shaded = f3(diffuse.x * diff_col.x * kdocc,
                   diffuse.y * diff_col.y * kdocc,
                   diffuse.z * diff_col.z * kdocc);

    // FG LUT (256x256x2), uv = (NdotV, roughness)
    float NdotV = fmaxf(vdotn, 0.0001f);
    float fg0, fg1;
    {
        const int W = 256, H = 256;
        float fx = NdotV * W - 0.5f;
        float fy = roughness * H - 0.5f;
        float x0f = floorf(fx), y0f = floorf(fy);
        float tx = fx - x0f, ty = fy - y0f;
        int x0 = min(max((int)x0f, 0), W - 1);
        int x1 = min(x0 + 1, W - 1);
        int y0 = min(max((int)y0f, 0), H - 1);
        int y1 = min(y0 + 1, H - 1);
        const float* p00 = fg_lut + ((size_t)y0 * W + x0) * 2;
        const float* p01 = fg_lut + ((size_t)y0 * W + x1) * 2;
        const float* p10 = fg_lut + ((size_t)y1 * W + x0) * 2;
        const float* p11 = fg_lut + ((size_t)y1 * W + x1) * 2;
        float w00 = (1.f - tx) * (1.f - ty);
        float w01 = tx * (1.f - ty);
        float w10 = (1.f - tx) * ty;
        float w11 = tx * ty;
        fg0 = __ldg(p00)   * w00 + __ldg(p01)   * w01 + __ldg(p10)   * w10 + __ldg(p11)   * w11;
        fg1 = __ldg(p00+1) * w00 + __ldg(p01+1) * w01 + __ldg(p10+1) * w10 + __ldg(p11+1) * w11;
    }

    // mip level
    const float MIN_R = 0.08f, MAX_R = 0.5f;
    const int L = 6;
    float rc_lo = fminf(fmaxf(roughness, MIN_R), MAX_R);
    float lo = (rc_lo - MIN_R) / (MAX_R - MIN_R) * (float)(L - 2);
    float rc_hi = fminf(fmaxf(roughness, MAX_R), 1.0f);
    float hi = (rc_hi - MAX_R) / (1.0f - MAX_R) + (float)(L - 2);
    float lvl = (roughness < MAX_R) ? lo : hi;
    lvl = fminf(fmaxf(lvl, 0.f), (float)(L - 1));
    int l0 = (int)floorf(lvl);
    int l1 = min(l0 + 1, L - 1);
    float lf = lvl - (float)l0;

    const float* mips[6] = { spec0, spec1, spec2, spec3, spec4, spec5 };
    const int    res [6] = { 512, 256, 128, 64, 32, 16 };

    F3 s0 = sample_cube(mips[l0], res[l0], refl);
    F3 s1 = sample_cube(mips[l1], res[l1], refl);
    F3 spec = f3(s0.x * (1.f - lf) + s1.x * lf,
                 s0.y * (1.f - lf) + s1.y * lf,
                 s0.z * (1.f - lf) + s1.z * lf);
    spec = f3(fmaxf(spec.x, 0.f), fmaxf(spec.y, 0.f), fmaxf(spec.z, 0.f));

    float so = 1.f - occ;
    F3 reflectance = f3(spec_col.x * fg0 + fg1,
                        spec_col.y * fg0 + fg1,
                        spec_col.z * fg0 + fg1);
    shaded = f3(shaded.x + spec.x * reflectance.x * so,
                shaded.y + spec.y * reflectance.y * so,
                shaded.z + spec.z * reflectance.z * so);

    float ox = srgb1(fminf(fmaxf(shaded.x, 0.f), 1.f));
    float oy = srgb1(fminf(fmaxf(shaded.y, 0.f), 1.f));
    float oz = srgb1(fminf(fmaxf(shaded.z, 0.f), 1.f));

    float* op = out + 3 * (size_t)i;
    op[0] = ox; op[1] = oy; op[2] = oz;
}

extern "C" void kernel_launch(void* const* d_in, const int* in_sizes, int n_in,
                              void* d_out, int out_size) {
    const float* view_dir    = (const float*)d_in[0];
    const float* normal      = (const float*)d_in[1];
    const float* kd          = (const float*)d_in[2];
    const float* ks          = (const float*)d_in[3];
    const float* reflect_occ = (const float*)d_in[4];
    const float* diffuse_map = (const float*)d_in[5];
    const float* spec0       = (const float*)d_in[6];
    const float* spec1       = (const float*)d_in[7];
    const float* spec2       = (const float*)d_in[8];
    const float* spec3       = (const float*)d_in[9];
    const float* spec4       = (const float*)d_in[10];
    const float* spec5       = (const float*)d_in[11];
    const float* fg_lut      = (const float*)d_in[12];
    float* out = (float*)d_out;

    int n = in_sizes[0] / 3;
    int threads = 256;
    int blocks = (n + threads - 1) / threads;
    envlight_kernel<<<blocks, threads>>>(view_dir, normal, kd, ks, reflect_occ,
                                         diffuse_map, spec0, spec1, spec2, spec3,
                                         spec4, spec5, fg_lut, out, n);
}

// round 3
// speedup vs baseline: 1.1644x; 1.1644x over previous
#include <cuda_runtime.h>
#include <math.h>

// ---------------------------------------------------------------------------
// Repacked texture scratch: all 6 spec mips + diffuse map as float4 texels.
// Spec level sizes (texels): 6*512^2, 6*256^2, ..., 6*16^2  => 2,096,640
// Diffuse: 6*16*16 = 1536. Total 2,098,176 float4 = ~33.6 MB.
// ---------------------------------------------------------------------------
#define SPEC_TOTAL 2096640
#define DIFF_OFF   SPEC_TOTAL
__device__ float4 g_tex[SPEC_TOTAL + 1536];

__constant__ int c_spec_off[6] = {0, 1572864, 1966080, 2064384, 2088960, 2095104};
__constant__ int c_spec_res[6] = {512, 256, 128, 64, 32, 16};

__global__ void repack_kernel(const float* __restrict__ src, int dst_off, int n) {
    int i = blockIdx.x * blockDim.x + threadIdx.x;
    if (i >= n) return;
    const float* p = src + 3 * (size_t)i;
    g_tex[dst_off + i] = make_float4(p[0], p[1], p[2], 0.f);
}

struct F3 { float x, y, z; };
__device__ __forceinline__ F3 f3(float a, float b, float c) { F3 r; r.x=a; r.y=b; r.z=c; return r; }

// Face/UV for cube sampling (resolution-independent part)
struct CubeUV { int face; float u, v; };

__device__ __forceinline__ CubeUV cube_face_uv(F3 d) {
    float ax = fabsf(d.x), ay = fabsf(d.y), az = fabsf(d.z);
    bool is_x = (ax >= ay) && (ax >= az);
    bool is_y = (!is_x) && (ay >= az);
    CubeUV r;
    float ma;
    if (is_x) {
        r.face = (d.x > 0.f) ? 0 : 1;
        ma = ax;
        r.u = (d.x > 0.f) ? -d.z : d.z;
        r.v = -d.y;
    } else if (is_y) {
        r.face = (d.y > 0.f) ? 2 : 3;
        ma = ay;
        r.u = d.x;
        r.v = (d.y > 0.f) ? d.z : -d.z;
    } else {
        r.face = (d.z > 0.f) ? 4 : 5;
        ma = az;
        r.u = d.x * ((d.z > 0.f) ? 1.f : -1.f);
        r.v = -d.y;
    }
    ma = fmaxf(ma, 1e-20f);
    r.u /= ma; r.v /= ma;
    return r;
}

// Bilinear gather from float4-packed cubemap at g_tex[off ...], resolution R
__device__ __forceinline__ F3 bilerp_cube(int off, int R, CubeUV cu) {
    float fu = (cu.u * 0.5f + 0.5f) * (float)R - 0.5f;
    float fv = (cu.v * 0.5f + 0.5f) * (float)R - 0.5f;
    float x0f = floorf(fu), y0f = floorf(fv);
    float tx = fu - x0f, ty = fv - y0f;
    int x0 = min(max((int)x0f, 0), R - 1);
    int x1 = min(x0 + 1, R - 1);
    int y0 = min(max((int)y0f, 0), R - 1);
    int y1 = min(y0 + 1, R - 1);

    int base = off + cu.face * R * R;
    const float4* t = g_tex;
    float4 c00 = __ldg(t + base + y0 * R + x0);
    float4 c01 = __ldg(t + base + y0 * R + x1);
    float4 c10 = __ldg(t + base + y1 * R + x0);
    float4 c11 = __ldg(t + base + y1 * R + x1);

    float w00 = (1.f - tx) * (1.f - ty);
    float w01 = tx * (1.f - ty);
    float w10 = (1.f - tx) * ty;
    float w11 = tx * ty;
    return f3(c00.x*w00 + c01.x*w01 + c10.x*w10 + c11.x*w11,
              c00.y*w00 + c01.y*w01 + c10.y*w10 + c11.y*w11,
              c00.z*w00 + c01.z*w01 + c10.z*w10 + c11.z*w11);
}

__device__ __forceinline__ float srgb1(float x) {
    if (x <= 0.0031308f) return 12.92f * x;
    return 1.055f * powf(fmaxf(x, 0.0031308f), 1.0f / 2.4f) - 0.055f;
}

// Each thread shades 4 consecutive points; streaming I/O via float4.
__global__ void envlight_kernel(
    const float* __restrict__ view_dir,
    const float* __restrict__ normal,
    const float* __restrict__ kd,
    const float* __restrict__ ks,
    const float* __restrict__ reflect_occ,
    const float* __restrict__ fg_lut,
    float* __restrict__ out,
    int ngroups)
{
    int t = blockIdx.x * blockDim.x + threadIdx.x;
    if (t >= ngroups) return;

    // 12 floats (4 points x 3) per array via 3 x LDG.128
    const float4* v4  = (const float4*)view_dir   + 3 * (size_t)t;
    const float4* n4  = (const float4*)normal     + 3 * (size_t)t;
    const float4* kd4 = (const float4*)kd         + 3 * (size_t)t;
    const float4* ks4 = (const float4*)ks         + 3 * (size_t)t;

    float vv[12], nn[12], dd[12], ss[12], oo[12];
    {
        float4 a = __ldg(v4), b = __ldg(v4 + 1), c = __ldg(v4 + 2);
        vv[0]=a.x; vv[1]=a.y; vv[2]=a.z; vv[3]=a.w; vv[4]=b.x; vv[5]=b.y;
        vv[6]=b.z; vv[7]=b.w; vv[8]=c.x; vv[9]=c.y; vv[10]=c.z; vv[11]=c.w;
    }
    {
        float4 a = __ldg(n4), b = __ldg(n4 + 1), c = __ldg(n4 + 2);
        nn[0]=a.x; nn[1]=a.y; nn[2]=a.z; nn[3]=a.w; nn[4]=b.x; nn[5]=b.y;
        nn[6]=b.z; nn[7]=b.w; nn[8]=c.x; nn[9]=c.y; nn[10]=c.z; nn[11]=c.w;
    }
    {
        float4 a = __ldg(kd4), b = __ldg(kd4 + 1), c = __ldg(kd4 + 2);
        dd[0]=a.x; dd[1]=a.y; dd[2]=a.z; dd[3]=a.w; dd[4]=b.x; dd[5]=b.y;
        dd[6]=b.z; dd[7]=b.w; dd[8]=c.x; dd[9]=c.y; dd[10]=c.z; dd[11]=c.w;
    }
    {
        float4 a = __ldg(ks4), b = __ldg(ks4 + 1), c = __ldg(ks4 + 2);
        ss[0]=a.x; ss[1]=a.y; ss[2]=a.z; ss[3]=a.w; ss[4]=b.x; ss[5]=b.y;
        ss[6]=b.z; ss[7]=b.w; ss[8]=c.x; ss[9]=c.y; ss[10]=c.z; ss[11]=c.w;
    }
    float4 occ4 = __ldg((const float4*)reflect_occ + t);
    float occA[4] = {occ4.x, occ4.y, occ4.z, occ4.w};

    #pragma unroll
    for (int p = 0; p < 4; p++) {
        F3 v   = f3(vv[3*p], vv[3*p+1], vv[3*p+2]);
        F3 nrm = f3(nn[3*p], nn[3*p+1], nn[3*p+2]);
        F3 kdv = f3(dd[3*p], dd[3*p+1], dd[3*p+2]);
        float ks0 = ss[3*p], roughness = ss[3*p+1], metallic = ss[3*p+2];
        float occ = occA[p];

        F3 spec_col = f3((1.f - metallic) * 0.04f + kdv.x * metallic,
                         (1.f - metallic) * 0.04f + kdv.y * metallic,
                         (1.f - metallic) * 0.04f + kdv.z * metallic);
        F3 diff_col = f3(kdv.x * (1.f - metallic), kdv.y * (1.f - metallic), kdv.z * (1.f - metallic));

        float vdotn = v.x * nrm.x + v.y * nrm.y + v.z * nrm.z;
        F3 refl = f3(2.f * vdotn * nrm.x - v.x,
                     2.f * vdotn * nrm.y - v.y,
                     2.f * vdotn * nrm.z - v.z);
        float rr = fmaxf(refl.x*refl.x + refl.y*refl.y + refl.z*refl.z, 1e-20f);
        float sq = sqrtf(rr);
        refl = f3(refl.x / sq, refl.y / sq, refl.z / sq);

        // diffuse from repacked 16^2 cubemap
        CubeUV cun = cube_face_uv(nrm);
        F3 diffuse = bilerp_cube(DIFF_OFF, 16, cun);
        diffuse = f3(fmaxf(diffuse.x, 0.f), fmaxf(diffuse.y, 0.f), fmaxf(diffuse.z, 0.f));
        float kdocc = 1.f - ks0;
        F3 shaded = f3(diffuse.x * diff_col.x * kdocc,
                       diffuse.y * diff_col.y * kdocc,
                       diffuse.z * diff_col.z * kdocc);

        // FG LUT 256x256x2 via float2 loads
        float NdotV = fmaxf(vdotn, 0.0001f);
        float fg0, fg1;
        {
            const int W = 256, H = 256;
            float fx = NdotV * W - 0.5f;
            float fy = roughness * H - 0.5f;
            float x0f = floorf(fx), y0f = floorf(fy);
            float tx = fx - x0f, ty = fy - y0f;
            int x0 = min(max((int)x0f, 0), W - 1);
            int x1 = min(x0 + 1, W - 1);
            int y0 = min(max((int)y0f, 0), H - 1);
            int y1 = min(y0 + 1, H - 1);
            const float2* L = (const float2*)fg_lut;
            float2 c00 = __ldg(L + y0 * W + x0);
            float2 c01 = __ldg(L + y0 * W + x1);
            float2 c10 = __ldg(L + y1 * W + x0);
            float2 c11 = __ldg(L + y1 * W + x1);
            float w00 = (1.f - tx) * (1.f - ty);
            float w01 = tx * (1.f - ty);
            float w10 = (1.f - tx) * ty;
            float w11 = tx * ty;
            fg0 = c00.x*w00 + c01.x*w01 + c10.x*w10 + c11.x*w11;
            fg1 = c00.y*w00 + c01.y*w01 + c10.y*w10 + c11.y*w11;
        }

        // mip level
        const float MIN_R = 0.08f, MAX_R = 0.5f;
        const int L = 6;
        float rc_lo = fminf(fmaxf(roughness, MIN_R), MAX_R);
        float lo = (rc_lo - MIN_R) / (MAX_R - MIN_R) * (float)(L - 2);
        float rc_hi = fminf(fmaxf(roughness, MAX_R), 1.0f);
        float hi = (rc_hi - MAX_R) / (1.0f - MAX_R) + (float)(L - 2);
        float lvl = (roughness < MAX_R) ? lo : hi;
        lvl = fminf(fmaxf(lvl, 0.f), (float)(L - 1));
        int l0 = (int)floorf(lvl);
        int l1 = min(l0 + 1, L - 1);
        float lf = lvl - (float)l0;

        // shared face/uv for both mip levels (same direction)
        CubeUV cur = cube_face_uv(refl);
        F3 s0 = bilerp_cube(c_spec_off[l0], c_spec_res[l0], cur);
        F3 s1 = bilerp_cube(c_spec_off[l1], c_spec_res[l1], cur);
        F3 spec = f3(s0.x + (s1.x - s0.x) * lf,
                     s0.y + (s1.y - s0.y) * lf,
                     s0.z + (s1.z - s0.z) * lf);
        // match reference blend exactly: a*(1-f)+b*f
        spec = f3(s0.x * (1.f - lf) + s1.x * lf,
                  s0.y * (1.f - lf) + s1.y * lf,
                  s0.z * (1.f - lf) + s1.z * lf);
        spec = f3(fmaxf(spec.x, 0.f), fmaxf(spec.y, 0.f), fmaxf(spec.z, 0.f));

        float so = 1.f - occ;
        float rx = spec_col.x * fg0 + fg1;
        float ry = spec_col.y * fg0 + fg1;
        float rz = spec_col.z * fg0 + fg1;
        oo[3*p]   = srgb1(fminf(fmaxf(shaded.x + spec.x * rx * so, 0.f), 1.f));
        oo[3*p+1] = srgb1(fminf(fmaxf(shaded.y + spec.y * ry * so, 0.f), 1.f));
        oo[3*p+2] = srgb1(fminf(fmaxf(shaded.z + spec.z * rz * so, 0.f), 1.f));
    }

    float4* o4 = (float4*)out + 3 * (size_t)t;
    o4[0] = make_float4(oo[0], oo[1], oo[2], oo[3]);
    o4[1] = make_float4(oo[4], oo[5], oo[6], oo[7]);
    o4[2] = make_float4(oo[8], oo[9], oo[10], oo[11]);
}

extern "C" void kernel_launch(void* const* d_in, const int* in_sizes, int n_in,
                              void* d_out, int out_size) {
    const float* view_dir    = (const float*)d_in[0];
    const float* normal      = (const float*)d_in[1];
    const float* kd          = (const float*)d_in[2];
    const float* ks          = (const float*)d_in[3];
    const float* reflect_occ = (const float*)d_in[4];
    const float* diffuse_map = (const float*)d_in[5];
    const float* specs[6] = {
        (const float*)d_in[6], (const float*)d_in[7], (const float*)d_in[8],
        (const float*)d_in[9], (const float*)d_in[10], (const float*)d_in[11]
    };
    const float* fg_lut = (const float*)d_in[12];
    float* out = (float*)d_out;

    // Repack spec mips + diffuse into float4 texels
    const int offs[6] = {0, 1572864, 1966080, 2064384, 2088960, 2095104};
    const int ress[6] = {512, 256, 128, 64, 32, 16};
    for (int l = 0; l < 6; l++) {
        int n = 6 * ress[l] * ress[l];
        repack_kernel<<<(n + 255) / 256, 256>>>(specs[l], offs[l], n);
    }
    {
        int n = 6 * 16 * 16;
        repack_kernel<<<(n + 255) / 256, 256>>>(diffuse_map, DIFF_OFF, n);
    }

    int n = in_sizes[0] / 3;          // 2,097,152 (divisible by 4)
    int ngroups = n / 4;
    int threads = 256;
    int blocks = (ngroups + threads - 1) / threads;
    envlight_kernel<<<blocks, threads>>>(view_dir, normal, kd, ks, reflect_occ,
                                         fg_lut, out, ngroups);
}

// round 4
// speedup vs baseline: 1.2812x; 1.1003x over previous
#include <cuda_runtime.h>
#include <math.h>

// ---------------------------------------------------------------------------
// Repacked texture scratch: all 6 spec mips + diffuse map as float4 texels.
// Spec level texel counts: 1572864, 393216, 98304, 24576, 6144, 1536.
// Offsets: 0, 1572864, 1966080, 2064384, 2088960, 2095104; total 2096640.
// Diffuse: 1536 at DIFF_OFF. Grand total 2,098,176 float4 = ~33.6 MB.
// ---------------------------------------------------------------------------
#define SPEC_TOTAL 2096640
#define DIFF_OFF   SPEC_TOTAL
#define TEX_TOTAL  (SPEC_TOTAL + 1536)
__device__ float4 g_tex[TEX_TOTAL];

__constant__ int c_spec_off[6] = {0, 1572864, 1966080, 2064384, 2088960, 2095104};
__constant__ int c_spec_res[6] = {512, 256, 128, 64, 32, 16};

// Single fused repack: one launch covers all mips + diffuse.
__global__ void repack_all_kernel(
    const float* __restrict__ s0, const float* __restrict__ s1,
    const float* __restrict__ s2, const float* __restrict__ s3,
    const float* __restrict__ s4, const float* __restrict__ s5,
    const float* __restrict__ dm)
{
    int i = blockIdx.x * blockDim.x + threadIdx.x;
    if (i >= TEX_TOTAL) return;
    const float* src; int local;
    if (i < 1572864)      { src = s0; local = i; }
    else if (i < 1966080) { src = s1; local = i - 1572864; }
    else if (i < 2064384) { src = s2; local = i - 1966080; }
    else if (i < 2088960) { src = s3; local = i - 2064384; }
    else if (i < 2095104) { src = s4; local = i - 2088960; }
    else if (i < 2096640) { src = s5; local = i - 2095104; }
    else                  { src = dm; local = i - 2096640; }
    const float* p = src + 3 * (size_t)local;
    g_tex[i] = make_float4(p[0], p[1], p[2], 0.f);
}

struct F3 { float x, y, z; };
__device__ __forceinline__ F3 f3(float a, float b, float c) { F3 r; r.x=a; r.y=b; r.z=c; return r; }

struct CubeUV { int face; float u, v; };

__device__ __forceinline__ CubeUV cube_face_uv(F3 d) {
    float ax = fabsf(d.x), ay = fabsf(d.y), az = fabsf(d.z);
    bool is_x = (ax >= ay) && (ax >= az);
    bool is_y = (!is_x) && (ay >= az);
    CubeUV r;
    float ma;
    if (is_x) {
        r.face = (d.x > 0.f) ? 0 : 1;
        ma = ax;
        r.u = (d.x > 0.f) ? -d.z : d.z;
        r.v = -d.y;
    } else if (is_y) {
        r.face = (d.y > 0.f) ? 2 : 3;
        ma = ay;
        r.u = d.x;
        r.v = (d.y > 0.f) ? d.z : -d.z;
    } else {
        r.face = (d.z > 0.f) ? 4 : 5;
        ma = az;
        r.u = d.x * ((d.z > 0.f) ? 1.f : -1.f);
        r.v = -d.y;
    }
    float inv_ma = 1.f / fmaxf(ma, 1e-20f);
    r.u *= inv_ma; r.v *= inv_ma;
    return r;
}

__device__ __forceinline__ F3 bilerp_cube(int off, int R, CubeUV cu) {
    float fu = fmaf(cu.u, 0.5f * (float)R, 0.5f * (float)R - 0.5f);
    float fv = fmaf(cu.v, 0.5f * (float)R, 0.5f * (float)R - 0.5f);
    float x0f = floorf(fu), y0f = floorf(fv);
    float tx = fu - x0f, ty = fv - y0f;
    int x0 = min(max((int)x0f, 0), R - 1);
    int x1 = min(x0 + 1, R - 1);
    int y0 = min(max((int)y0f, 0), R - 1);
    int y1 = min(y0 + 1, R - 1);

    int base = off + cu.face * R * R;
    const float4* t = g_tex;
    float4 c00 = __ldg(t + base + y0 * R + x0);
    float4 c01 = __ldg(t + base + y0 * R + x1);
    float4 c10 = __ldg(t + base + y1 * R + x0);
    float4 c11 = __ldg(t + base + y1 * R + x1);

    float w00 = (1.f - tx) * (1.f - ty);
    float w01 = tx * (1.f - ty);
    float w10 = (1.f - tx) * ty;
    float w11 = tx * ty;
    return f3(c00.x*w00 + c01.x*w01 + c10.x*w10 + c11.x*w11,
              c00.y*w00 + c01.y*w01 + c10.y*w10 + c11.y*w11,
              c00.z*w00 + c01.z*w01 + c10.z*w10 + c11.z*w11);
}

// Fast sRGB: reference clamps the pow argument to >= 0.0031308, so MUFU
// log2/exp2 are always in a well-conditioned range (~1e-6 rel error).
__device__ __forceinline__ float srgb1(float x) {
    float lin = 12.92f * x;
    float xa = fmaxf(x, 0.0031308f);
    float g = 1.055f * exp2f(__log2f(xa) * (1.0f / 2.4f)) - 0.055f;
    return (x <= 0.0031308f) ? lin : g;
}

__global__ void envlight_kernel(
    const float* __restrict__ view_dir,
    const float* __restrict__ normal,
    const float* __restrict__ kd,
    const float* __restrict__ ks,
    const float* __restrict__ reflect_occ,
    const float* __restrict__ fg_lut,
    float* __restrict__ out,
    int ngroups)
{
    int t = blockIdx.x * blockDim.x + threadIdx.x;
    if (t >= ngroups) return;

    const float4* v4  = (const float4*)view_dir   + 3 * (size_t)t;
    const float4* n4  = (const float4*)normal     + 3 * (size_t)t;
    const float4* kd4 = (const float4*)kd         + 3 * (size_t)t;
    const float4* ks4 = (const float4*)ks         + 3 * (size_t)t;

    float vv[12], nn[12], dd[12], ss[12], oo[12];
    {
        float4 a = __ldg(v4), b = __ldg(v4 + 1), c = __ldg(v4 + 2);
        vv[0]=a.x; vv[1]=a.y; vv[2]=a.z; vv[3]=a.w; vv[4]=b.x; vv[5]=b.y;
        vv[6]=b.z; vv[7]=b.w; vv[8]=c.x; vv[9]=c.y; vv[10]=c.z; vv[11]=c.w;
    }
    {
        float4 a = __ldg(n4), b = __ldg(n4 + 1), c = __ldg(n4 + 2);
        nn[0]=a.x; nn[1]=a.y; nn[2]=a.z; nn[3]=a.w; nn[4]=b.x; nn[5]=b.y;
        nn[6]=b.z; nn[7]=b.w; nn[8]=c.x; nn[9]=c.y; nn[10]=c.z; nn[11]=c.w;
    }
    {
        float4 a = __ldg(kd4), b = __ldg(kd4 + 1), c = __ldg(kd4 + 2);
        dd[0]=a.x; dd[1]=a.y; dd[2]=a.z; dd[3]=a.w; dd[4]=b.x; dd[5]=b.y;
        dd[6]=b.z; dd[7]=b.w; dd[8]=c.x; dd[9]=c.y; dd[10]=c.z; dd[11]=c.w;
    }
    {
        float4 a = __ldg(ks4), b = __ldg(ks4 + 1), c = __ldg(ks4 + 2);
        ss[0]=a.x; ss[1]=a.y; ss[2]=a.z; ss[3]=a.w; ss[4]=b.x; ss[5]=b.y;
        ss[6]=b.z; ss[7]=b.w; ss[8]=c.x; ss[9]=c.y; ss[10]=c.z; ss[11]=c.w;
    }
    float4 occ4 = __ldg((const float4*)reflect_occ + t);
    float occA[4] = {occ4.x, occ4.y, occ4.z, occ4.w};

    #pragma unroll
    for (int p = 0; p < 4; p++) {
        F3 v   = f3(vv[3*p], vv[3*p+1], vv[3*p+2]);
        F3 nrm = f3(nn[3*p], nn[3*p+1], nn[3*p+2]);
        F3 kdv = f3(dd[3*p], dd[3*p+1], dd[3*p+2]);
        float ks0 = ss[3*p], roughness = ss[3*p+1], metallic = ss[3*p+2];
        float occ = occA[p];

        F3 spec_col = f3((1.f - metallic) * 0.04f + kdv.x * metallic,
                         (1.f - metallic) * 0.04f + kdv.y * metallic,
                         (1.f - metallic) * 0.04f + kdv.z * metallic);
        F3 diff_col = f3(kdv.x * (1.f - metallic), kdv.y * (1.f - metallic), kdv.z * (1.f - metallic));

        float vdotn = v.x * nrm.x + v.y * nrm.y + v.z * nrm.z;
        F3 refl = f3(2.f * vdotn * nrm.x - v.x,
                     2.f * vdotn * nrm.y - v.y,
                     2.f * vdotn * nrm.z - v.z);
        float rr = fmaxf(refl.x*refl.x + refl.y*refl.y + refl.z*refl.z, 1e-20f);
        float rinv = rsqrtf(rr);
        refl = f3(refl.x * rinv, refl.y * rinv, refl.z * rinv);

        // diffuse from repacked 16^2 cubemap (L1-resident)
        CubeUV cun = cube_face_uv(nrm);
        F3 diffuse = bilerp_cube(DIFF_OFF, 16, cun);
        diffuse = f3(fmaxf(diffuse.x, 0.f), fmaxf(diffuse.y, 0.f), fmaxf(diffuse.z, 0.f));
        float kdocc = 1.f - ks0;
        F3 shaded = f3(diffuse.x * diff_col.x * kdocc,
                       diffuse.y * diff_col.y * kdocc,
                       diffuse.z * diff_col.z * kdocc);

        // FG LUT 256x256x2 via float2 loads
        float NdotV = fmaxf(vdotn, 0.0001f);
        float fg0, fg1;
        {
            const int W = 256, H = 256;
            float fx = NdotV * W - 0.5f;
            float fy = roughness * H - 0.5f;
            float x0f = floorf(fx), y0f = floorf(fy);
            float tx = fx - x0f, ty = fy - y0f;
            int x0 = min(max((int)x0f, 0), W - 1);
            int x1 = min(x0 + 1, W - 1);
            int y0 = min(max((int)y0f, 0), H - 1);
            int y1 = min(y0 + 1, H - 1);
            const float2* L = (const float2*)fg_lut;
            float2 c00 = __ldg(L + y0 * W + x0);
            float2 c01 = __ldg(L + y0 * W + x1);
            float2 c10 = __ldg(L + y1 * W + x0);
            float2 c11 = __ldg(L + y1 * W + x1);
            float w00 = (1.f - tx) * (1.f - ty);
            float w01 = tx * (1.f - ty);
            float w10 = (1.f - tx) * ty;
            float w11 = tx * ty;
            fg0 = c00.x*w00 + c01.x*w01 + c10.x*w10 + c11.x*w11;
            fg1 = c00.y*w00 + c01.y*w01 + c10.y*w10 + c11.y*w11;
        }

        // mip level selection
        const float MIN_R = 0.08f, MAX_R = 0.5f;
        const int L = 6;
        float rc_lo = fminf(fmaxf(roughness, MIN_R), MAX_R);
        float lo = (rc_lo - MIN_R) * ((float)(L - 2) / (MAX_R - MIN_R));
        float rc_hi = fminf(fmaxf(roughness, MAX_R), 1.0f);
        float hi = (rc_hi - MAX_R) * (1.0f / (1.0f - MAX_R)) + (float)(L - 2);
        float lvl = (roughness < MAX_R) ? lo : hi;
        lvl = fminf(fmaxf(lvl, 0.f), (float)(L - 1));
        int l0 = (int)floorf(lvl);
        int l1 = min(l0 + 1, L - 1);
        float lf = lvl - (float)l0;

        CubeUV cur = cube_face_uv(refl);
        F3 s0 = bilerp_cube(c_spec_off[l0], c_spec_res[l0], cur);
        F3 s1 = bilerp_cube(c_spec_off[l1], c_spec_res[l1], cur);
        F3 spec = f3(s0.x * (1.f - lf) + s1.x * lf,
                     s0.y * (1.f - lf) + s1.y * lf,
                     s0.z * (1.f - lf) + s1.z * lf);
        spec = f3(fmaxf(spec.x, 0.f), fmaxf(spec.y, 0.f), fmaxf(spec.z, 0.f));

        float so = 1.f - occ;
        float rx = spec_col.x * fg0 + fg1;
        float ry = spec_col.y * fg0 + fg1;
        float rz = spec_col.z * fg0 + fg1;
        oo[3*p]   = srgb1(fminf(fmaxf(shaded.x + spec.x * rx * so, 0.f), 1.f));
        oo[3*p+1] = srgb1(fminf(fmaxf(shaded.y + spec.y * ry * so, 0.f), 1.f));
        oo[3*p+2] = srgb1(fminf(fmaxf(shaded.z + spec.z * rz * so, 0.f), 1.f));
    }

    float4* o4 = (float4*)out + 3 * (size_t)t;
    o4[0] = make_float4(oo[0], oo[1], oo[2], oo[3]);
    o4[1] = make_float4(oo[4], oo[5], oo[6], oo[7]);
    o4[2] = make_float4(oo[8], oo[9], oo[10], oo[11]);
}

extern "C" void kernel_launch(void* const* d_in, const int* in_sizes, int n_in,
                              void* d_out, int out_size) {
    const float* view_dir    = (const float*)d_in[0];
    const float* normal      = (const float*)d_in[1];
    const float* kd          = (const float*)d_in[2];
    const float* ks          = (const float*)d_in[3];
    const float* reflect_occ = (const float*)d_in[4];
    const float* diffuse_map = (const float*)d_in[5];
    const float* fg_lut      = (const float*)d_in[12];
    float* out = (float*)d_out;

    // One fused repack launch for all mips + diffuse
    {
        int threads = 256;
        int blocks = (TEX_TOTAL + threads - 1) / threads;
        repack_all_kernel<<<blocks, threads>>>(
            (const float*)d_in[6], (const float*)d_in[7], (const float*)d_in[8],
            (const float*)d_in[9], (const float*)d_in[10], (const float*)d_in[11],
            diffuse_map);
    }

    int n = in_sizes[0] / 3;          // 2,097,152 (divisible by 4)
    int ngroups = n / 4;
    int threads = 256;
    int blocks = (ngroups + threads - 1) / threads;
    envlight_kernel<<<blocks, threads>>>(view_dir, normal, kd, ks, reflect_occ,
                                         fg_lut, out, ngroups);
}

// round 5
// speedup vs baseline: 1.4596x; 1.1393x over previous
#include <cuda_runtime.h>
#include <cuda_fp16.h>
#include <math.h>

// ---------------------------------------------------------------------------
// Repacked texture scratch: all 6 spec mips + diffuse map as float4 texels.
// Spec texel counts: 1572864, 393216, 98304, 24576, 6144, 1536 (total 2096640).
// Offsets: 0, 1572864, 1966080, 2064384, 2088960, 2095104. Diffuse at DIFF_OFF.
// ---------------------------------------------------------------------------
#define SPEC_TOTAL 2096640
#define DIFF_OFF   SPEC_TOTAL
#define TEX_TOTAL  (SPEC_TOTAL + 1536)
#define MIP4_OFF   2088960
#define MIP5_OFF   2095104
__device__ float4 g_tex[TEX_TOTAL];

__constant__ int c_spec_off[6] = {0, 1572864, 1966080, 2064384, 2088960, 2095104};
__constant__ int c_spec_res[6] = {512, 256, 128, 64, 32, 16};

__global__ void repack_all_kernel(
    const float* __restrict__ s0, const float* __restrict__ s1,
    const float* __restrict__ s2, const float* __restrict__ s3,
    const float* __restrict__ s4, const float* __restrict__ s5,
    const float* __restrict__ dm)
{
    int i = blockIdx.x * blockDim.x + threadIdx.x;
    if (i >= TEX_TOTAL) return;
    const float* src; int local;
    if (i < 1572864)      { src = s0; local = i; }
    else if (i < 1966080) { src = s1; local = i - 1572864; }
    else if (i < 2064384) { src = s2; local = i - 1966080; }
    else if (i < 2088960) { src = s3; local = i - 2064384; }
    else if (i < 2095104) { src = s4; local = i - 2088960; }
    else if (i < 2096640) { src = s5; local = i - 2095104; }
    else                  { src = dm; local = i - 2096640; }
    const float* p = src + 3 * (size_t)local;
    g_tex[i] = make_float4(p[0], p[1], p[2], 0.f);
}

struct F3 { float x, y, z; };
__device__ __forceinline__ F3 f3(float a, float b, float c) { F3 r; r.x=a; r.y=b; r.z=c; return r; }

struct CubeUV { int face; float u, v; };

__device__ __forceinline__ CubeUV cube_face_uv(F3 d) {
    float ax = fabsf(d.x), ay = fabsf(d.y), az = fabsf(d.z);
    bool is_x = (ax >= ay) && (ax >= az);
    bool is_y = (!is_x) && (ay >= az);
    CubeUV r;
    float ma;
    if (is_x) {
        r.face = (d.x > 0.f) ? 0 : 1;
        ma = ax;
        r.u = (d.x > 0.f) ? -d.z : d.z;
        r.v = -d.y;
    } else if (is_y) {
        r.face = (d.y > 0.f) ? 2 : 3;
        ma = ay;
        r.u = d.x;
        r.v = (d.y > 0.f) ? d.z : -d.z;
    } else {
        r.face = (d.z > 0.f) ? 4 : 5;
        ma = az;
        r.u = d.x * ((d.z > 0.f) ? 1.f : -1.f);
        r.v = -d.y;
    }
    float inv_ma = 1.f / fmaxf(ma, 1e-20f);
    r.u *= inv_ma; r.v *= inv_ma;
    return r;
}

struct BilinIdx { int i00, i01, i10, i11; float w00, w01, w10, w11; };

__device__ __forceinline__ BilinIdx bilin_idx(int R, CubeUV cu) {
    float fu = fmaf(cu.u, 0.5f * (float)R, 0.5f * (float)R - 0.5f);
    float fv = fmaf(cu.v, 0.5f * (float)R, 0.5f * (float)R - 0.5f);
    float x0f = floorf(fu), y0f = floorf(fv);
    float tx = fu - x0f, ty = fv - y0f;
    int x0 = min(max((int)x0f, 0), R - 1);
    int x1 = min(x0 + 1, R - 1);
    int y0 = min(max((int)y0f, 0), R - 1);
    int y1 = min(y0 + 1, R - 1);
    int base = cu.face * R * R;
    BilinIdx b;
    b.i00 = base + y0 * R + x0;
    b.i01 = base + y0 * R + x1;
    b.i10 = base + y1 * R + x0;
    b.i11 = base + y1 * R + x1;
    b.w00 = (1.f - tx) * (1.f - ty);
    b.w01 = tx * (1.f - ty);
    b.w10 = (1.f - tx) * ty;
    b.w11 = tx * ty;
    return b;
}

__device__ __forceinline__ F3 blend4(float4 c00, float4 c01, float4 c10, float4 c11, BilinIdx b) {
    return f3(c00.x*b.w00 + c01.x*b.w01 + c10.x*b.w10 + c11.x*b.w11,
              c00.y*b.w00 + c01.y*b.w01 + c10.y*b.w10 + c11.y*b.w11,
              c00.z*b.w00 + c01.z*b.w01 + c10.z*b.w10 + c11.z*b.w11);
}

__device__ __forceinline__ F3 bilerp_global(int off, int R, CubeUV cu) {
    BilinIdx b = bilin_idx(R, cu);
    const float4* t = g_tex + off;
    return blend4(__ldg(t + b.i00), __ldg(t + b.i01), __ldg(t + b.i10), __ldg(t + b.i11), b);
}

__device__ __forceinline__ F3 bilerp_smem_f4(const float4* __restrict__ s, int R, CubeUV cu) {
    BilinIdx b = bilin_idx(R, cu);
    return blend4(s[b.i00], s[b.i01], s[b.i10], s[b.i11], b);
}

__device__ __forceinline__ float4 h4_to_f4(ushort4 u) {
    return make_float4(__half2float(__ushort_as_half(u.x)),
                       __half2float(__ushort_as_half(u.y)),
                       __half2float(__ushort_as_half(u.z)), 0.f);
}

__device__ __forceinline__ F3 bilerp_smem_h4(const ushort4* __restrict__ s, int R, CubeUV cu) {
    BilinIdx b = bilin_idx(R, cu);
    return blend4(h4_to_f4(s[b.i00]), h4_to_f4(s[b.i01]),
                  h4_to_f4(s[b.i10]), h4_to_f4(s[b.i11]), b);
}

__device__ __forceinline__ F3 sample_spec_level(int l, CubeUV cu,
                                                const float4* __restrict__ s_mip5,
                                                const ushort4* __restrict__ s_mip4) {
    if (l <= 3) return bilerp_global(c_spec_off[l], c_spec_res[l], cu);
    if (l == 4) return bilerp_smem_h4(s_mip4, 32, cu);
    return bilerp_smem_f4(s_mip5, 16, cu);
}

__device__ __forceinline__ float srgb1(float x) {
    float lin = 12.92f * x;
    float xa = fmaxf(x, 0.0031308f);
    float g = 1.055f * exp2f(__log2f(xa) * (1.0f / 2.4f)) - 0.055f;
    return (x <= 0.0031308f) ? lin : g;
}

#define THREADS 256
#define GRIDB   304   // 2 blocks per SM on GB300 (152 SMs)

__global__ __launch_bounds__(THREADS, 2)
void envlight_kernel(
    const float* __restrict__ view_dir,
    const float* __restrict__ normal,
    const float* __restrict__ kd,
    const float* __restrict__ ks,
    const float* __restrict__ reflect_occ,
    const float* __restrict__ fg_lut,
    float* __restrict__ out,
    int ngroups)
{
    extern __shared__ unsigned char smem_raw[];
    float4*  s_diff = (float4*)smem_raw;                 // 1536 * 16B = 24KB
    float4*  s_mip5 = s_diff + 1536;                     // 1536 * 16B = 24KB
    ushort4* s_mip4 = (ushort4*)(s_mip5 + 1536);         // 6144 *  8B = 48KB

    // Fill shared copies (once per persistent block)
    for (int i = threadIdx.x; i < 1536; i += THREADS) {
        s_diff[i] = g_tex[DIFF_OFF + i];
        s_mip5[i] = g_tex[MIP5_OFF + i];
    }
    for (int i = threadIdx.x; i < 6144; i += THREADS) {
        float4 v = g_tex[MIP4_OFF + i];
        s_mip4[i] = make_ushort4(__half_as_ushort(__float2half_rn(v.x)),
                                 __half_as_ushort(__float2half_rn(v.y)),
                                 __half_as_ushort(__float2half_rn(v.z)), 0);
    }
    __syncthreads();

    for (int t = blockIdx.x * THREADS + threadIdx.x; t < ngroups; t += GRIDB * THREADS) {
        const float4* v4  = (const float4*)view_dir   + 3 * (size_t)t;
        const float4* n4  = (const float4*)normal     + 3 * (size_t)t;
        const float4* kd4 = (const float4*)kd         + 3 * (size_t)t;
        const float4* ks4 = (const float4*)ks         + 3 * (size_t)t;

        float vv[12], nn[12], dd[12], ss[12], oo[12];
        {
            float4 a = __ldg(v4), b = __ldg(v4 + 1), c = __ldg(v4 + 2);
            vv[0]=a.x; vv[1]=a.y; vv[2]=a.z; vv[3]=a.w; vv[4]=b.x; vv[5]=b.y;
            vv[6]=b.z; vv[7]=b.w; vv[8]=c.x; vv[9]=c.y; vv[10]=c.z; vv[11]=c.w;
        }
        {
            float4 a = __ldg(n4), b = __ldg(n4 + 1), c = __ldg(n4 + 2);
            nn[0]=a.x; nn[1]=a.y; nn[2]=a.z; nn[3]=a.w; nn[4]=b.x; nn[5]=b.y;
            nn[6]=b.z; nn[7]=b.w; nn[8]=c.x; nn[9]=c.y; nn[10]=c.z; nn[11]=c.w;
        }
        {
            float4 a = __ldg(kd4), b = __ldg(kd4 + 1), c = __ldg(kd4 + 2);
            dd[0]=a.x; dd[1]=a.y; dd[2]=a.z; dd[3]=a.w; dd[4]=b.x; dd[5]=b.y;
            dd[6]=b.z; dd[7]=b.w; dd[8]=c.x; dd[9]=c.y; dd[10]=c.z; dd[11]=c.w;
        }
        {
            float4 a = __ldg(ks4), b = __ldg(ks4 + 1), c = __ldg(ks4 + 2);
            ss[0]=a.x; ss[1]=a.y; ss[2]=a.z; ss[3]=a.w; ss[4]=b.x; ss[5]=b.y;
            ss[6]=b.z; ss[7]=b.w; ss[8]=c.x; ss[9]=c.y; ss[10]=c.z; ss[11]=c.w;
        }
        float4 occ4 = __ldg((const float4*)reflect_occ + t);
        float occA[4] = {occ4.x, occ4.y, occ4.z, occ4.w};

        #pragma unroll
        for (int p = 0; p < 4; p++) {
            F3 v   = f3(vv[3*p], vv[3*p+1], vv[3*p+2]);
            F3 nrm = f3(nn[3*p], nn[3*p+1], nn[3*p+2]);
            F3 kdv = f3(dd[3*p], dd[3*p+1], dd[3*p+2]);
            float ks0 = ss[3*p], roughness = ss[3*p+1], metallic = ss[3*p+2];
            float occ = occA[p];

            F3 spec_col = f3((1.f - metallic) * 0.04f + kdv.x * metallic,
                             (1.f - metallic) * 0.04f + kdv.y * metallic,
                             (1.f - metallic) * 0.04f + kdv.z * metallic);
            F3 diff_col = f3(kdv.x * (1.f - metallic), kdv.y * (1.f - metallic), kdv.z * (1.f - metallic));

            float vdotn = v.x * nrm.x + v.y * nrm.y + v.z * nrm.z;
            F3 refl = f3(2.f * vdotn * nrm.x - v.x,
                         2.f * vdotn * nrm.y - v.y,
                         2.f * vdotn * nrm.z - v.z);
            float rr = fmaxf(refl.x*refl.x + refl.y*refl.y + refl.z*refl.z, 1e-20f);
            float rinv = rsqrtf(rr);
            refl = f3(refl.x * rinv, refl.y * rinv, refl.z * rinv);

            // diffuse from smem 16^2 cubemap
            CubeUV cun = cube_face_uv(nrm);
            F3 diffuse = bilerp_smem_f4(s_diff, 16, cun);
            diffuse = f3(fmaxf(diffuse.x, 0.f), fmaxf(diffuse.y, 0.f), fmaxf(diffuse.z, 0.f));
            float kdocc = 1.f - ks0;
            F3 shaded = f3(diffuse.x * diff_col.x * kdocc,
                           diffuse.y * diff_col.y * kdocc,
                           diffuse.z * diff_col.z * kdocc);

            // FG LUT 256x256x2 via float2 loads (global, L2-resident)
            float NdotV = fmaxf(vdotn, 0.0001f);
            float fg0, fg1;
            {
                const int W = 256, H = 256;
                float fx = NdotV * W - 0.5f;
                float fy = roughness * H - 0.5f;
                float x0f = floorf(fx), y0f = floorf(fy);
                float tx = fx - x0f, ty = fy - y0f;
                int x0 = min(max((int)x0f, 0), W - 1);
                int x1 = min(x0 + 1, W - 1);
                int y0 = min(max((int)y0f, 0), H - 1);
                int y1 = min(y0 + 1, H - 1);
                const float2* L = (const float2*)fg_lut;
                float2 c00 = __ldg(L + y0 * W + x0);
                float2 c01 = __ldg(L + y0 * W + x1);
                float2 c10 = __ldg(L + y1 * W + x0);
                float2 c11 = __ldg(L + y1 * W + x1);
                float w00 = (1.f - tx) * (1.f - ty);
                float w01 = tx * (1.f - ty);
                float w10 = (1.f - tx) * ty;
                float w11 = tx * ty;
                fg0 = c00.x*w00 + c01.x*w01 + c10.x*w10 + c11.x*w11;
                fg1 = c00.y*w00 + c01.y*w01 + c10.y*w10 + c11.y*w11;
            }

            // mip level selection
            const float MIN_R = 0.08f, MAX_R = 0.5f;
            const int L = 6;
            float rc_lo = fminf(fmaxf(roughness, MIN_R), MAX_R);
            float lo = (rc_lo - MIN_R) * ((float)(L - 2) / (MAX_R - MIN_R));
            float rc_hi = fminf(fmaxf(roughness, MAX_R), 1.0f);
            float hi = (rc_hi - MAX_R) * (1.0f / (1.0f - MAX_R)) + (float)(L - 2);
            float lvl = (roughness < MAX_R) ? lo : hi;
            lvl = fminf(fmaxf(lvl, 0.f), (float)(L - 1));
            int l0 = (int)floorf(lvl);
            int l1 = min(l0 + 1, L - 1);
            float lf = lvl - (float)l0;

            CubeUV cur = cube_face_uv(refl);
            F3 s0 = sample_spec_level(l0, cur, s_mip5, s_mip4);
            F3 s1 = sample_spec_level(l1, cur, s_mip5, s_mip4);
            F3 spec = f3(s0.x * (1.f - lf) + s1.x * lf,
                         s0.y * (1.f - lf) + s1.y * lf,
                         s0.z * (1.f - lf) + s1.z * lf);
            spec = f3(fmaxf(spec.x, 0.f), fmaxf(spec.y, 0.f), fmaxf(spec.z, 0.f));

            float so = 1.f - occ;
            float rx = spec_col.x * fg0 + fg1;
            float ry = spec_col.y * fg0 + fg1;
            float rz = spec_col.z * fg0 + fg1;
            oo[3*p]   = srgb1(fminf(fmaxf(shaded.x + spec.x * rx * so, 0.f), 1.f));
            oo[3*p+1] = srgb1(fminf(fmaxf(shaded.y + spec.y * ry * so, 0.f), 1.f));
            oo[3*p+2] = srgb1(fminf(fmaxf(shaded.z + spec.z * rz * so, 0.f), 1.f));
        }

        float4* o4 = (float4*)out + 3 * (size_t)t;
        o4[0] = make_float4(oo[0], oo[1], oo[2], oo[3]);
        o4[1] = make_float4(oo[4], oo[5], oo[6], oo[7]);
        o4[2] = make_float4(oo[8], oo[9], oo[10], oo[11]);
    }
}

#define SMEM_BYTES (1536*16 + 1536*16 + 6144*8)   // 96 KB

extern "C" void kernel_launch(void* const* d_in, const int* in_sizes, int n_in,
                              void* d_out, int out_size) {
    const float* view_dir    = (const float*)d_in[0];
    const float* normal      = (const float*)d_in[1];
    const float* kd          = (const float*)d_in[2];
    const float* ks          = (const float*)d_in[3];
    const float* reflect_occ = (const float*)d_in[4];
    const float* diffuse_map = (const float*)d_in[5];
    const float* fg_lut      = (const float*)d_in[12];
    float* out = (float*)d_out;

    cudaFuncSetAttribute(envlight_kernel,
                         cudaFuncAttributeMaxDynamicSharedMemorySize, SMEM_BYTES);

    // One fused repack launch for all mips + diffuse
    {
        int threads = 256;
        int blocks = (TEX_TOTAL + threads - 1) / threads;
        repack_all_kernel<<<blocks, threads>>>(
            (const float*)d_in[6], (const float*)d_in[7], (const float*)d_in[8],
            (const float*)d_in[9], (const float*)d_in[10], (const float*)d_in[11],
            diffuse_map);
    }

    int n = in_sizes[0] / 3;          // 2,097,152 (divisible by 4)
    int ngroups = n / 4;
    envlight_kernel<<<GRIDB, THREADS, SMEM_BYTES>>>(view_dir, normal, kd, ks, reflect_occ,
                                                    fg_lut, out, ngroups);
}